// round 16
// baseline (speedup 1.0000x reference)
#include <cuda_runtime.h>
#include <cuda_fp16.h>
#include <math.h>
#include <stdint.h>

// Problem constants
#define Bz   2
#define Lz   2048
#define Ez   1024
#define Hz   16
#define Dz   64
#define BLz  (Bz*Lz)          // 4096 rows
#define E3z  (3*Ez)           // 3072
#define FFz  (4*Ez)           // 4096

// ---------------- static device scratch (no allocations allowed) ----------------
__device__ __half g_h    [(size_t)BLz*Ez];
__device__ __half g_qkv  [(size_t)BLz*E3z];
__device__ __half g_att  [(size_t)BLz*Ez];
__device__ float  g_x1   [(size_t)BLz*Ez];
__device__ __half g_ffn  [(size_t)BLz*FFz];
__device__ __half g_wqkvT[(size_t)E3z*Ez];
__device__ __half g_wprojT[(size_t)Ez*Ez];
__device__ __half g_w1T  [(size_t)FFz*Ez];
__device__ __half g_w2T  [(size_t)Ez*FFz];

// ---------------- helpers ----------------
static __device__ __forceinline__ void mma_fp16(
    float* c, const uint32_t* a, const uint32_t* b)
{
    asm volatile(
        "mma.sync.aligned.m16n8k16.row.col.f32.f16.f16.f32 "
        "{%0,%1,%2,%3}, {%4,%5,%6,%7}, {%8,%9}, {%0,%1,%2,%3};"
        : "+f"(c[0]), "+f"(c[1]), "+f"(c[2]), "+f"(c[3])
        : "r"(a[0]), "r"(a[1]), "r"(a[2]), "r"(a[3]),
          "r"(b[0]), "r"(b[1]));
}
#define LDSM_X4(r0, r1, r2, r3, addr) \
    asm volatile("ldmatrix.sync.aligned.m8n8.x4.shared.b16 {%0,%1,%2,%3}, [%4];" \
        : "=r"(r0), "=r"(r1), "=r"(r2), "=r"(r3) : "r"(addr))
#define LDSM_X4_T(r0, r1, r2, r3, addr) \
    asm volatile("ldmatrix.sync.aligned.m8n8.x4.trans.shared.b16 {%0,%1,%2,%3}, [%4];" \
        : "=r"(r0), "=r"(r1), "=r"(r2), "=r"(r3) : "r"(addr))
#define CP16(dst_u32, src_ptr) \
    asm volatile("cp.async.cg.shared.global [%0], [%1], 16;" \
                 :: "r"(dst_u32), "l"(src_ptr))
#define CP_COMMIT()  asm volatile("cp.async.commit_group;" ::: "memory")
#define CP_WAIT1()   asm volatile("cp.async.wait_group 1;" ::: "memory")
#define CP_WAIT0()   asm volatile("cp.async.wait_group 0;" ::: "memory")

// ---------------- fp16 mma.sync GEMM: 128x256 tile, BK=64, 3-stage, 1 CTA/SM ----------------
// 8 warps, warp tile 64x64 (4 mt x 8 nt): 32 MMAs per 8-LDSM batch per ks.
enum { EPI_NONE = 0, EPI_BIAS_RES = 1, EPI_BIAS_GELU = 2 };

#define SLDH 72   // smem row stride in halves

template<int EPI, bool OUT_HALF>
__global__ void __launch_bounds__(256, 1)
mma_gemm(const __half* __restrict__ A, const __half* __restrict__ B, void* __restrict__ Cv,
         const float* __restrict__ bias, const float* __restrict__ res,
         int K, int lda, int ldb, int ldc)
{
    extern __shared__ __half smh[];
    // 3 stages, each: A 128xSLDH then B 256xSLDH
    const int STG = (128 + 256) * SLDH;

    int tid  = threadIdx.x;
    int lane = tid & 31;
    int wid  = tid >> 5;
    int warp_m = wid & 1;     // 2 warps along m (64 rows each)
    int warp_n = wid >> 1;    // 4 warps along n (64 cols each)

    int m0 = blockIdx.y * 128;
    int n0 = blockIdx.x * 256;

    uint32_t Sm_u = (uint32_t)__cvta_generic_to_shared(smh);

    int lm_g = lane >> 3, lm_r = lane & 7;
    int aRow  = warp_m * 64 + (lm_g & 1) * 8 + lm_r;   // + mt*16
    int aColH = (lm_g >> 1) * 8;                       // + ks*16
    int bRow  = warp_n * 64 + (lm_g >> 1) * 8 + lm_r;  // + ntp*16
    int bColH = (lm_g & 1) * 8;                        // + ks*16

    float acc[4][8][4];
    #pragma unroll
    for (int i = 0; i < 4; i++)
        #pragma unroll
        for (int j = 0; j < 8; j++)
            #pragma unroll
            for (int k = 0; k < 4; k++) acc[i][j][k] = 0.f;

    const int slabs = K >> 6;   // BK = 64

    auto issue = [&](int s, int buf) {
        int k0 = s << 6;
        uint32_t base = Sm_u + (uint32_t)(buf * STG) * 2;
        #pragma unroll
        for (int i = 0; i < 4; i++) {              // A: 128 rows x 64 halves
            int e = tid + i * 256, row = e >> 3, c8 = e & 7;
            CP16(base + (uint32_t)(row * SLDH + c8 * 8) * 2,
                 &A[(long long)(m0 + row) * lda + k0 + c8 * 8]);
        }
        #pragma unroll
        for (int i = 0; i < 8; i++) {              // B: 256 rows x 64 halves
            int e = tid + i * 256, row = e >> 3, c8 = e & 7;
            CP16(base + (uint32_t)(128 * SLDH + row * SLDH + c8 * 8) * 2,
                 &B[(long long)(n0 + row) * ldb + k0 + c8 * 8]);
        }
    };

    issue(0, 0); CP_COMMIT();
    issue(1, 1); CP_COMMIT();

    int qr = lane >> 2, qc = lane & 3;
    int cur = 0;
    for (int s = 0; s < slabs; s++) {
        if (s + 1 < slabs) { CP_WAIT1(); } else { CP_WAIT0(); }
        __syncthreads();

        int nxt = cur + 2; if (nxt >= 3) nxt -= 3;
        if (s + 2 < slabs) { issue(s + 2, nxt); CP_COMMIT(); }

        uint32_t aBase = Sm_u + (uint32_t)(cur * STG + aRow * SLDH + aColH) * 2;
        uint32_t bBase = Sm_u + (uint32_t)(cur * STG + 128 * SLDH + bRow * SLDH + bColH) * 2;

        #pragma unroll
        for (int ks = 0; ks < 4; ks++) {
            uint32_t af[4][4];
            #pragma unroll
            for (int mt = 0; mt < 4; mt++)
                LDSM_X4(af[mt][0], af[mt][1], af[mt][2], af[mt][3],
                        aBase + (uint32_t)(mt * 16 * SLDH + ks * 16) * 2);
            uint32_t bf[8][2];
            #pragma unroll
            for (int ntp = 0; ntp < 4; ntp++)
                LDSM_X4(bf[2 * ntp][0], bf[2 * ntp][1], bf[2 * ntp + 1][0], bf[2 * ntp + 1][1],
                        bBase + (uint32_t)(ntp * 16 * SLDH + ks * 16) * 2);
            #pragma unroll
            for (int mt = 0; mt < 4; mt++)
                #pragma unroll
                for (int nt = 0; nt < 8; nt++)
                    mma_fp16(acc[mt][nt], af[mt], bf[nt]);
        }
        cur = cur + 1; if (cur == 3) cur = 0;
    }

    float*  Cf = reinterpret_cast<float*>(Cv);
    __half* Ch = reinterpret_cast<__half*>(Cv);

    #pragma unroll
    for (int mt = 0; mt < 4; mt++) {
        #pragma unroll
        for (int nt = 0; nt < 8; nt++) {
            int gc = n0 + warp_n * 64 + nt * 8 + qc * 2;
            #pragma unroll
            for (int half_i = 0; half_i < 2; half_i++) {
                long long gr = m0 + warp_m * 64 + mt * 16 + qr + half_i * 8;
                float v0 = acc[mt][nt][half_i * 2 + 0];
                float v1 = acc[mt][nt][half_i * 2 + 1];
                if (EPI == EPI_BIAS_RES) {
                    v0 += bias[gc]     + res[gr * ldc + gc];
                    v1 += bias[gc + 1] + res[gr * ldc + gc + 1];
                }
                if (EPI == EPI_BIAS_GELU) {
                    v0 += bias[gc];
                    v1 += bias[gc + 1];
                    v0 = 0.5f * v0 * (1.f + erff(v0 * 0.70710678118654752f));
                    v1 = 0.5f * v1 * (1.f + erff(v1 * 0.70710678118654752f));
                }
                if (OUT_HALF)
                    *reinterpret_cast<__half2*>(&Ch[gr * ldc + gc]) = __floats2half2_rn(v0, v1);
                else
                    *reinterpret_cast<float2*>(&Cf[gr * ldc + gc]) = make_float2(v0, v1);
            }
        }
    }
}

// ---------------- fp16 flash attention: register softmax, ldmatrix(+trans V) ----------------
#define QLDH 72

__global__ void __launch_bounds__(256, 2)
flash_k(const __half* __restrict__ qkv, __half* __restrict__ att)
{
    extern __shared__ __half smh[];
    __half* Qs = smh;               // 128 x QLDH
    __half* Ks = Qs + 128 * QLDH;   // 64  x QLDH
    __half* Vs = Ks + 64 * QLDH;    // 64  x QLDH (key-major)

    int tid  = threadIdx.x;
    int lane = tid & 31;
    int wid  = tid >> 5;
    int qr = lane >> 2, qc = lane & 3;

    int bb = blockIdx.y >> 4;       // Hz = 16
    int hh = blockIdx.y & 15;
    int q0 = blockIdx.x * 128;
    const float CEXP = 1.4426950408889634f / 32.f;   // log2(e)/sqrt(E)

    const __half* Qg = qkv + (size_t)bb * Lz * E3z + hh * Dz;
    const __half* Kg = qkv + (size_t)bb * Lz * E3z + Ez + hh * Dz;
    const __half* Vg = qkv + (size_t)bb * Lz * E3z + 2 * Ez + hh * Dz;

    uint32_t Qs_u = (uint32_t)__cvta_generic_to_shared(Qs);
    uint32_t Ks_u = (uint32_t)__cvta_generic_to_shared(Ks);
    uint32_t Vs_u = (uint32_t)__cvta_generic_to_shared(Vs);

    int lm_g = lane >> 3, lm_r = lane & 7;
    uint32_t qBase = Qs_u + (uint32_t)((wid * 16 + (lm_g & 1) * 8 + lm_r) * QLDH
                                        + (lm_g >> 1) * 8) * 2;
    uint32_t kBase = Ks_u + (uint32_t)(((lm_g >> 1) * 8 + lm_r) * QLDH + (lm_g & 1) * 8) * 2;
    uint32_t vBase = Vs_u + (uint32_t)(((lm_g & 1) * 8 + lm_r) * QLDH + (lm_g >> 1) * 8) * 2;

    #pragma unroll
    for (int i = 0; i < 4; i++) {
        int e = tid + i * 256, row = e >> 3, c8 = e & 7;
        *reinterpret_cast<float4*>(&Qs[row * QLDH + c8 * 8]) =
            *reinterpret_cast<const float4*>(&Qg[(size_t)(q0 + row) * E3z + c8 * 8]);
    }

    float o[8][4];
    #pragma unroll
    for (int nt = 0; nt < 8; nt++)
        #pragma unroll
        for (int k = 0; k < 4; k++) o[nt][k] = 0.f;
    float m0 = -INFINITY, m1 = -INFINITY, l0 = 0.f, l1 = 0.f;

    for (int kt = 0; kt < 32; kt++) {
        __syncthreads();

        #pragma unroll
        for (int i = 0; i < 2; i++) {
            int e = tid + i * 256, row = e >> 3, c8 = e & 7;
            *reinterpret_cast<float4*>(&Ks[row * QLDH + c8 * 8]) =
                *reinterpret_cast<const float4*>(&Kg[(size_t)(kt * 64 + row) * E3z + c8 * 8]);
        }
        #pragma unroll
        for (int i = 0; i < 2; i++) {
            int e = tid + i * 256, row = e >> 3, c8 = e & 7;
            *reinterpret_cast<float4*>(&Vs[row * QLDH + c8 * 8]) =
                *reinterpret_cast<const float4*>(&Vg[(size_t)(kt * 64 + row) * E3z + c8 * 8]);
        }
        __syncthreads();

        float s[8][4];
        #pragma unroll
        for (int nt = 0; nt < 8; nt++)
            #pragma unroll
            for (int k = 0; k < 4; k++) s[nt][k] = 0.f;

        #pragma unroll
        for (int ks = 0; ks < 4; ks++) {
            uint32_t a[4];
            LDSM_X4(a[0], a[1], a[2], a[3], qBase + (uint32_t)(ks * 16) * 2);
            uint32_t b[8][2];
            #pragma unroll
            for (int ntp = 0; ntp < 4; ntp++)
                LDSM_X4(b[2 * ntp][0], b[2 * ntp][1], b[2 * ntp + 1][0], b[2 * ntp + 1][1],
                        kBase + (uint32_t)(ntp * 16 * QLDH + ks * 16) * 2);
            #pragma unroll
            for (int nt = 0; nt < 8; nt++)
                mma_fp16(s[nt], a, b[nt]);
        }

        float mx0 = -INFINITY, mx1 = -INFINITY;
        #pragma unroll
        for (int nt = 0; nt < 8; nt++) {
            mx0 = fmaxf(mx0, fmaxf(s[nt][0], s[nt][1]));
            mx1 = fmaxf(mx1, fmaxf(s[nt][2], s[nt][3]));
        }
        mx0 = fmaxf(mx0, __shfl_xor_sync(0xffffffffu, mx0, 1));
        mx0 = fmaxf(mx0, __shfl_xor_sync(0xffffffffu, mx0, 2));
        mx1 = fmaxf(mx1, __shfl_xor_sync(0xffffffffu, mx1, 1));
        mx1 = fmaxf(mx1, __shfl_xor_sync(0xffffffffu, mx1, 2));

        float mn0 = fmaxf(m0, mx0), mn1 = fmaxf(m1, mx1);
        float f0 = exp2f((m0 - mn0) * CEXP);
        float f1 = exp2f((m1 - mn1) * CEXP);

        float sum0 = 0.f, sum1 = 0.f;
        uint32_t p0[8], p1[8];
        #pragma unroll
        for (int nt = 0; nt < 8; nt++) {
            float e0 = exp2f((s[nt][0] - mn0) * CEXP);
            float e1 = exp2f((s[nt][1] - mn0) * CEXP);
            float e2 = exp2f((s[nt][2] - mn1) * CEXP);
            float e3 = exp2f((s[nt][3] - mn1) * CEXP);
            sum0 += e0 + e1;
            sum1 += e2 + e3;
            __half2 h0 = __floats2half2_rn(e0, e1);
            __half2 h1 = __floats2half2_rn(e2, e3);
            p0[nt] = *reinterpret_cast<uint32_t*>(&h0);
            p1[nt] = *reinterpret_cast<uint32_t*>(&h1);
        }
        sum0 += __shfl_xor_sync(0xffffffffu, sum0, 1);
        sum0 += __shfl_xor_sync(0xffffffffu, sum0, 2);
        sum1 += __shfl_xor_sync(0xffffffffu, sum1, 1);
        sum1 += __shfl_xor_sync(0xffffffffu, sum1, 2);

        l0 = l0 * f0 + sum0;  m0 = mn0;
        l1 = l1 * f1 + sum1;  m1 = mn1;

        #pragma unroll
        for (int nt = 0; nt < 8; nt++) {
            o[nt][0] *= f0; o[nt][1] *= f0;
            o[nt][2] *= f1; o[nt][3] *= f1;
        }

        #pragma unroll
        for (int kt2 = 0; kt2 < 4; kt2++) {
            uint32_t a[4] = { p0[2 * kt2], p1[2 * kt2], p0[2 * kt2 + 1], p1[2 * kt2 + 1] };
            uint32_t b[8][2];
            #pragma unroll
            for (int ntp = 0; ntp < 4; ntp++)
                LDSM_X4_T(b[2 * ntp][0], b[2 * ntp][1], b[2 * ntp + 1][0], b[2 * ntp + 1][1],
                          vBase + (uint32_t)(kt2 * 16 * QLDH + ntp * 16) * 2);
            #pragma unroll
            for (int nt = 0; nt < 8; nt++)
                mma_fp16(o[nt], a, b[nt]);
        }
    }

    float i0 = 1.f / l0, i1 = 1.f / l1;
    size_t r0g = (size_t)bb * Lz + q0 + wid * 16 + qr;
    #pragma unroll
    for (int nt = 0; nt < 8; nt++) {
        int col = hh * Dz + nt * 8 + 2 * qc;
        *reinterpret_cast<__half2*>(&att[r0g * Ez + col]) =
            __floats2half2_rn(o[nt][0] * i0, o[nt][1] * i0);
        *reinterpret_cast<__half2*>(&att[(r0g + 8) * Ez + col]) =
            __floats2half2_rn(o[nt][2] * i1, o[nt][3] * i1);
    }
}

// ---------------- fused prep: LN1 + all 4 weight transposes in ONE launch ----------------
static __device__ __forceinline__ void dev_transpose(
    const float* __restrict__ src, __half* __restrict__ dst,
    int lds, int ldd, int bx, int by, float (*t)[33])
{
    int r0 = by * 32, c0 = bx * 32;
    int x = threadIdx.x & 31, y4 = (threadIdx.x >> 5) * 4;
    #pragma unroll
    for (int i = 0; i < 4; i++)
        t[y4 + i][x] = src[(long long)(r0 + y4 + i) * lds + c0 + x];
    __syncthreads();
    #pragma unroll
    for (int i = 0; i < 4; i++)
        dst[(long long)(c0 + y4 + i) * ldd + r0 + x] = __float2half_rn(t[x][y4 + i]);
}

static __device__ __forceinline__ void dev_ln(
    const float* __restrict__ x, const float* __restrict__ g,
    const float* __restrict__ b, __half* __restrict__ y, long long row,
    float* sh_s, float* sh_q)
{
    const float* xr = x + row * Ez;
    int t = threadIdx.x;

    float4 v = reinterpret_cast<const float4*>(xr)[t];
    float s  = v.x + v.y + v.z + v.w;
    float sq = v.x * v.x + v.y * v.y + v.z * v.z + v.w * v.w;
    #pragma unroll
    for (int o = 16; o > 0; o >>= 1) {
        s  += __shfl_down_sync(0xffffffffu, s,  o);
        sq += __shfl_down_sync(0xffffffffu, sq, o);
    }
    int warp = t >> 5, lane = t & 31;
    if (lane == 0) { sh_s[warp] = s; sh_q[warp] = sq; }
    __syncthreads();
    if (warp == 0) {
        s  = (lane < 8) ? sh_s[lane] : 0.f;
        sq = (lane < 8) ? sh_q[lane] : 0.f;
        #pragma unroll
        for (int o = 4; o > 0; o >>= 1) {
            s  += __shfl_down_sync(0xffffffffu, s,  o);
            sq += __shfl_down_sync(0xffffffffu, sq, o);
        }
        if (lane == 0) { sh_s[0] = s; sh_q[0] = sq; }
    }
    __syncthreads();
    float mu  = sh_s[0] * (1.f / Ez);
    float var = sh_q[0] * (1.f / Ez) - mu * mu;
    float inv = rsqrtf(var + 1e-5f);

    float4 gg = reinterpret_cast<const float4*>(g)[t];
    float4 bb = reinterpret_cast<const float4*>(b)[t];
    __half2 o0 = __floats2half2_rn((v.x - mu) * inv * gg.x + bb.x,
                                   (v.y - mu) * inv * gg.y + bb.y);
    __half2 o1 = __floats2half2_rn((v.z - mu) * inv * gg.z + bb.z,
                                   (v.w - mu) * inv * gg.w + bb.w);
    uint2 pk = make_uint2(*reinterpret_cast<uint32_t*>(&o0),
                          *reinterpret_cast<uint32_t*>(&o1));
    reinterpret_cast<uint2*>(y + row * Ez)[t] = pk;
}

__global__ void __launch_bounds__(256) prep_k(
    const float* __restrict__ x, const float* __restrict__ ln1_g, const float* __restrict__ ln1_b,
    __half* __restrict__ h,
    const float* __restrict__ Wqkv, __half* __restrict__ wqkvT,
    const float* __restrict__ Wproj, __half* __restrict__ wprojT,
    const float* __restrict__ W1, __half* __restrict__ w1T,
    const float* __restrict__ W2, __half* __restrict__ w2T)
{
    __shared__ float tbuf[32][33];
    __shared__ float sh_s[8];
    __shared__ float sh_q[8];

    int bid = blockIdx.x;
    if (bid < BLz) {
        dev_ln(x, ln1_g, ln1_b, h, bid, sh_s, sh_q);
        return;
    }
    bid -= BLz;
    if (bid < (E3z / 32) * (Ez / 32)) {
        dev_transpose(Wqkv, wqkvT, E3z, Ez, bid % (E3z / 32), bid / (E3z / 32), tbuf);
        return;
    }
    bid -= (E3z / 32) * (Ez / 32);
    if (bid < (Ez / 32) * (Ez / 32)) {
        dev_transpose(Wproj, wprojT, Ez, Ez, bid % (Ez / 32), bid / (Ez / 32), tbuf);
        return;
    }
    bid -= (Ez / 32) * (Ez / 32);
    if (bid < (FFz / 32) * (Ez / 32)) {
        dev_transpose(W1, w1T, FFz, Ez, bid % (FFz / 32), bid / (FFz / 32), tbuf);
        return;
    }
    bid -= (FFz / 32) * (Ez / 32);
    {
        dev_transpose(W2, w2T, Ez, FFz, bid % (Ez / 32), bid / (Ez / 32), tbuf);
    }
}

// ---------------- LayerNorm (standalone, for LN2) ----------------
__global__ __launch_bounds__(256) void ln_k(
    const float* __restrict__ x, const float* __restrict__ g,
    const float* __restrict__ b, __half* __restrict__ y)
{
    __shared__ float sh_s[8];
    __shared__ float sh_q[8];
    dev_ln(x, g, b, y, blockIdx.x, sh_s, sh_q);
}

// ---------------- driver ----------------
extern "C" void kernel_launch(void* const* d_in, const int* in_sizes, int n_in,
                              void* d_out, int out_size)
{
    (void)in_sizes; (void)n_in; (void)out_size;
    const float* x      = (const float*)d_in[0];
    const float* ln1_g  = (const float*)d_in[1];
    const float* ln1_b  = (const float*)d_in[2];
    const float* W_qkv  = (const float*)d_in[3];
    const float* W_proj = (const float*)d_in[4];
    const float* b_proj = (const float*)d_in[5];
    const float* ln2_g  = (const float*)d_in[6];
    const float* ln2_b  = (const float*)d_in[7];
    const float* W1     = (const float*)d_in[8];
    const float* b1     = (const float*)d_in[9];
    const float* W2     = (const float*)d_in[10];
    const float* b2     = (const float*)d_in[11];
    float* out = (float*)d_out;

    __half *h, *qkv, *att, *ffn, *wqkvT, *wprojT, *w1T, *w2T;
    float *x1;
    cudaGetSymbolAddress((void**)&h,      g_h);
    cudaGetSymbolAddress((void**)&qkv,    g_qkv);
    cudaGetSymbolAddress((void**)&att,    g_att);
    cudaGetSymbolAddress((void**)&x1,     g_x1);
    cudaGetSymbolAddress((void**)&ffn,    g_ffn);
    cudaGetSymbolAddress((void**)&wqkvT,  g_wqkvT);
    cudaGetSymbolAddress((void**)&wprojT, g_wprojT);
    cudaGetSymbolAddress((void**)&w1T,    g_w1T);
    cudaGetSymbolAddress((void**)&w2T,    g_w2T);

    const int SMG = 3 * (128 + 256) * SLDH * 2;        // 165888 bytes (3-stage, 128x256)
    const int FLASH_SMEM = (128 + 64 + 64) * QLDH * 2; // 36864 bytes
    cudaFuncSetAttribute(mma_gemm<EPI_NONE,      true >, cudaFuncAttributeMaxDynamicSharedMemorySize, SMG);
    cudaFuncSetAttribute(mma_gemm<EPI_BIAS_RES,  false>, cudaFuncAttributeMaxDynamicSharedMemorySize, SMG);
    cudaFuncSetAttribute(mma_gemm<EPI_BIAS_GELU, true >, cudaFuncAttributeMaxDynamicSharedMemorySize, SMG);
    cudaFuncSetAttribute(flash_k, cudaFuncAttributeMaxDynamicSharedMemorySize, FLASH_SMEM);

    // 1. prep: LN1 + all weight transposes, one launch
    const int PREP_BLOCKS = BLz + (E3z / 32) * (Ez / 32) + (Ez / 32) * (Ez / 32)
                          + (FFz / 32) * (Ez / 32) + (Ez / 32) * (FFz / 32);
    prep_k<<<PREP_BLOCKS, 256>>>(x, ln1_g, ln1_b, h,
                                 W_qkv, wqkvT, W_proj, wprojT, W1, w1T, W2, w2T);

    // 2. qkv = fp16(h @ W_qkv)            grid (3072/256, 4096/128) = (12, 32)
    mma_gemm<EPI_NONE, true><<<dim3(E3z / 256, BLz / 128, 1), 256, SMG>>>(
        h, wqkvT, qkv, nullptr, nullptr, Ez, Ez, Ez, E3z);

    // 3. att = flash(Q, K, V)
    flash_k<<<dim3(Lz / 128, Bz * Hz), 256, FLASH_SMEM>>>(qkv, att);

    // 4. x1 = x + att @ W_proj + b_proj   grid (1024/256, 32) = (4, 32)
    mma_gemm<EPI_BIAS_RES, false><<<dim3(Ez / 256, BLz / 128, 1), 256, SMG>>>(
        att, wprojT, x1, b_proj, x, Ez, Ez, Ez, Ez);

    // 5. h = fp16(LN2(x1))
    ln_k<<<BLz, 256>>>(x1, ln2_g, ln2_b, h);

    // 6. ffn = fp16(gelu(h @ W1 + b1))    grid (4096/256, 32) = (16, 32)
    mma_gemm<EPI_BIAS_GELU, true><<<dim3(FFz / 256, BLz / 128, 1), 256, SMG>>>(
        h, w1T, ffn, b1, nullptr, Ez, Ez, Ez, FFz);

    // 7. out = x1 + ffn @ W2 + b2         grid (4, 32)
    mma_gemm<EPI_BIAS_RES, false><<<dim3(Ez / 256, BLz / 128, 1), 256, SMG>>>(
        ffn, w2T, out, b2, x1, FFz, FFz, FFz, Ez);
}

// round 17
// speedup vs baseline: 1.0813x; 1.0813x over previous
#include <cuda_runtime.h>
#include <cuda_fp16.h>
#include <math.h>
#include <stdint.h>

// Problem constants
#define Bz   2
#define Lz   2048
#define Ez   1024
#define Hz   16
#define Dz   64
#define BLz  (Bz*Lz)          // 4096 rows
#define E3z  (3*Ez)           // 3072
#define FFz  (4*Ez)           // 4096

// ---------------- static device scratch (no allocations allowed) ----------------
__device__ __half g_h    [(size_t)BLz*Ez];
__device__ __half g_qkv  [(size_t)BLz*E3z];
__device__ __half g_att  [(size_t)BLz*Ez];
__device__ float  g_x1   [(size_t)BLz*Ez];
__device__ __half g_ffn  [(size_t)BLz*FFz];
__device__ __half g_wqkvT[(size_t)E3z*Ez];
__device__ __half g_wprojT[(size_t)Ez*Ez];
__device__ __half g_w1T  [(size_t)FFz*Ez];
__device__ __half g_w2T  [(size_t)Ez*FFz];

// ---------------- helpers ----------------
static __device__ __forceinline__ void mma_fp16(
    float* c, const uint32_t* a, const uint32_t* b)
{
    asm volatile(
        "mma.sync.aligned.m16n8k16.row.col.f32.f16.f16.f32 "
        "{%0,%1,%2,%3}, {%4,%5,%6,%7}, {%8,%9}, {%0,%1,%2,%3};"
        : "+f"(c[0]), "+f"(c[1]), "+f"(c[2]), "+f"(c[3])
        : "r"(a[0]), "r"(a[1]), "r"(a[2]), "r"(a[3]),
          "r"(b[0]), "r"(b[1]));
}
#define LDSM_X4(r0, r1, r2, r3, addr) \
    asm volatile("ldmatrix.sync.aligned.m8n8.x4.shared.b16 {%0,%1,%2,%3}, [%4];" \
        : "=r"(r0), "=r"(r1), "=r"(r2), "=r"(r3) : "r"(addr))
#define LDSM_X4_T(r0, r1, r2, r3, addr) \
    asm volatile("ldmatrix.sync.aligned.m8n8.x4.trans.shared.b16 {%0,%1,%2,%3}, [%4];" \
        : "=r"(r0), "=r"(r1), "=r"(r2), "=r"(r3) : "r"(addr))
#define CP16(dst_u32, src_ptr) \
    asm volatile("cp.async.cg.shared.global [%0], [%1], 16;" \
                 :: "r"(dst_u32), "l"(src_ptr))
#define CP_COMMIT()  asm volatile("cp.async.commit_group;" ::: "memory")
#define CP_WAIT1()   asm volatile("cp.async.wait_group 1;" ::: "memory")
#define CP_WAIT0()   asm volatile("cp.async.wait_group 0;" ::: "memory")

// ---------------- fp16 mma.sync GEMM: 128x128 tile, BK=64, 3-stage (R15 proven) ----------------
enum { EPI_NONE = 0, EPI_BIAS_RES = 1, EPI_BIAS_GELU = 2 };

#define SLDH 72   // smem row stride in halves

template<int EPI, bool OUT_HALF>
__global__ void __launch_bounds__(256, 2)
mma_gemm(const __half* __restrict__ A, const __half* __restrict__ B, void* __restrict__ Cv,
         const float* __restrict__ bias, const float* __restrict__ res,
         int K, int lda, int ldb, int ldc)
{
    extern __shared__ __half smh[];
    const int STG = 2 * 128 * SLDH;

    int tid  = threadIdx.x;
    int lane = tid & 31;
    int wid  = tid >> 5;
    int warp_m = wid & 1;
    int warp_n = wid >> 1;

    int m0 = blockIdx.y * 128;
    int n0 = blockIdx.x * 128;

    uint32_t Sm_u = (uint32_t)__cvta_generic_to_shared(smh);

    int lm_g = lane >> 3, lm_r = lane & 7;
    int aRow  = warp_m * 64 + (lm_g & 1) * 8 + lm_r;
    int aColH = (lm_g >> 1) * 8;
    int bRow  = warp_n * 32 + (lm_g >> 1) * 8 + lm_r;
    int bColH = (lm_g & 1) * 8;

    float acc[4][4][4];
    #pragma unroll
    for (int i = 0; i < 4; i++)
        #pragma unroll
        for (int j = 0; j < 4; j++)
            #pragma unroll
            for (int k = 0; k < 4; k++) acc[i][j][k] = 0.f;

    const int slabs = K >> 6;   // BK = 64

    auto issue = [&](int s, int buf) {
        int k0 = s << 6;
        uint32_t base = Sm_u + (uint32_t)(buf * STG) * 2;
        #pragma unroll
        for (int i = 0; i < 4; i++) {
            int e = tid + i * 256, row = e >> 3, c8 = e & 7;
            CP16(base + (uint32_t)(row * SLDH + c8 * 8) * 2,
                 &A[(long long)(m0 + row) * lda + k0 + c8 * 8]);
        }
        #pragma unroll
        for (int i = 0; i < 4; i++) {
            int e = tid + i * 256, row = e >> 3, c8 = e & 7;
            CP16(base + (uint32_t)(128 * SLDH + row * SLDH + c8 * 8) * 2,
                 &B[(long long)(n0 + row) * ldb + k0 + c8 * 8]);
        }
    };

    issue(0, 0); CP_COMMIT();
    issue(1, 1); CP_COMMIT();

    int qr = lane >> 2, qc = lane & 3;
    int cur = 0;
    for (int s = 0; s < slabs; s++) {
        if (s + 1 < slabs) { CP_WAIT1(); } else { CP_WAIT0(); }
        __syncthreads();

        int nxt = cur + 2; if (nxt >= 3) nxt -= 3;
        if (s + 2 < slabs) { issue(s + 2, nxt); CP_COMMIT(); }

        uint32_t aBase = Sm_u + (uint32_t)(cur * STG + aRow * SLDH + aColH) * 2;
        uint32_t bBase = Sm_u + (uint32_t)(cur * STG + 128 * SLDH + bRow * SLDH + bColH) * 2;

        #pragma unroll
        for (int ks = 0; ks < 4; ks++) {
            uint32_t af[4][4];
            #pragma unroll
            for (int mt = 0; mt < 4; mt++)
                LDSM_X4(af[mt][0], af[mt][1], af[mt][2], af[mt][3],
                        aBase + (uint32_t)(mt * 16 * SLDH + ks * 16) * 2);
            uint32_t bf[4][2];
            #pragma unroll
            for (int ntp = 0; ntp < 2; ntp++)
                LDSM_X4(bf[2 * ntp][0], bf[2 * ntp][1], bf[2 * ntp + 1][0], bf[2 * ntp + 1][1],
                        bBase + (uint32_t)(ntp * 16 * SLDH + ks * 16) * 2);
            #pragma unroll
            for (int mt = 0; mt < 4; mt++)
                #pragma unroll
                for (int nt = 0; nt < 4; nt++)
                    mma_fp16(acc[mt][nt], af[mt], bf[nt]);
        }
        cur = cur + 1; if (cur == 3) cur = 0;
    }

    float*  Cf = reinterpret_cast<float*>(Cv);
    __half* Ch = reinterpret_cast<__half*>(Cv);

    #pragma unroll
    for (int mt = 0; mt < 4; mt++) {
        #pragma unroll
        for (int nt = 0; nt < 4; nt++) {
            int gc = n0 + warp_n * 32 + nt * 8 + qc * 2;
            #pragma unroll
            for (int half_i = 0; half_i < 2; half_i++) {
                long long gr = m0 + warp_m * 64 + mt * 16 + qr + half_i * 8;
                float v0 = acc[mt][nt][half_i * 2 + 0];
                float v1 = acc[mt][nt][half_i * 2 + 1];
                if (EPI == EPI_BIAS_RES) {
                    v0 += bias[gc]     + res[gr * ldc + gc];
                    v1 += bias[gc + 1] + res[gr * ldc + gc + 1];
                }
                if (EPI == EPI_BIAS_GELU) {
                    v0 += bias[gc];
                    v1 += bias[gc + 1];
                    v0 = 0.5f * v0 * (1.f + erff(v0 * 0.70710678118654752f));
                    v1 = 0.5f * v1 * (1.f + erff(v1 * 0.70710678118654752f));
                }
                if (OUT_HALF)
                    *reinterpret_cast<__half2*>(&Ch[gr * ldc + gc]) = __floats2half2_rn(v0, v1);
                else
                    *reinterpret_cast<float2*>(&Cf[gr * ldc + gc]) = make_float2(v0, v1);
            }
        }
    }
}

// ---------------- fp16 flash attention: register softmax + cp.async K/V pipeline ----------------
// Grid: (Lz/128, Bz*Hz). 256 threads, 2 CTAs/SM. K/V tiles double-buffered via cp.async,
// issued one tile ahead so global latency overlaps previous tile's compute.
#define QLDH 72
#define KVSTG (2 * 64 * QLDH)   // one stage: K tile then V tile

__global__ void __launch_bounds__(256, 2)
flash_k(const __half* __restrict__ qkv, __half* __restrict__ att)
{
    extern __shared__ __half smh[];
    __half* Qs  = smh;                  // 128 x QLDH
    __half* KV0 = Qs + 128 * QLDH;      // stage 0: K 64xQLDH, V 64xQLDH
    // stage 1 follows at KV0 + KVSTG

    int tid  = threadIdx.x;
    int lane = tid & 31;
    int wid  = tid >> 5;
    int qr = lane >> 2, qc = lane & 3;

    int bb = blockIdx.y >> 4;       // Hz = 16
    int hh = blockIdx.y & 15;
    int q0 = blockIdx.x * 128;
    const float CEXP = 1.4426950408889634f / 32.f;   // log2(e)/sqrt(E)

    const __half* Qg = qkv + (size_t)bb * Lz * E3z + hh * Dz;
    const __half* Kg = qkv + (size_t)bb * Lz * E3z + Ez + hh * Dz;
    const __half* Vg = qkv + (size_t)bb * Lz * E3z + 2 * Ez + hh * Dz;

    uint32_t Qs_u  = (uint32_t)__cvta_generic_to_shared(Qs);
    uint32_t KV_u  = (uint32_t)__cvta_generic_to_shared(KV0);

    int lm_g = lane >> 3, lm_r = lane & 7;
    uint32_t qBase = Qs_u + (uint32_t)((wid * 16 + (lm_g & 1) * 8 + lm_r) * QLDH
                                        + (lm_g >> 1) * 8) * 2;
    // offsets within a KV stage
    uint32_t kOff = (uint32_t)(((lm_g >> 1) * 8 + lm_r) * QLDH + (lm_g & 1) * 8) * 2;
    uint32_t vOff = (uint32_t)(64 * QLDH + ((lm_g & 1) * 8 + lm_r) * QLDH + (lm_g >> 1) * 8) * 2;

    // Q tile (128 x 64 halves) via cp.async, grouped with KV stage 0
    #pragma unroll
    for (int i = 0; i < 4; i++) {
        int e = tid + i * 256, row = e >> 3, c8 = e & 7;
        CP16(Qs_u + (uint32_t)(row * QLDH + c8 * 8) * 2,
             &Qg[(size_t)(q0 + row) * E3z + c8 * 8]);
    }

    auto issue_kv = [&](int kt, int buf) {
        uint32_t base = KV_u + (uint32_t)(buf * KVSTG) * 2;
        #pragma unroll
        for (int i = 0; i < 2; i++) {      // K: 64 rows x 64 halves
            int e = tid + i * 256, row = e >> 3, c8 = e & 7;
            CP16(base + (uint32_t)(row * QLDH + c8 * 8) * 2,
                 &Kg[(size_t)(kt * 64 + row) * E3z + c8 * 8]);
        }
        #pragma unroll
        for (int i = 0; i < 2; i++) {      // V: 64 rows x 64 halves (key-major)
            int e = tid + i * 256, row = e >> 3, c8 = e & 7;
            CP16(base + (uint32_t)(64 * QLDH + row * QLDH + c8 * 8) * 2,
                 &Vg[(size_t)(kt * 64 + row) * E3z + c8 * 8]);
        }
    };

    issue_kv(0, 0); CP_COMMIT();   // group 0 (includes Q)
    issue_kv(1, 1); CP_COMMIT();   // group 1

    float o[8][4];
    #pragma unroll
    for (int nt = 0; nt < 8; nt++)
        #pragma unroll
        for (int k = 0; k < 4; k++) o[nt][k] = 0.f;
    float m0 = -INFINITY, m1 = -INFINITY, l0 = 0.f, l1 = 0.f;

    for (int kt = 0; kt < 32; kt++) {
        if (kt + 1 < 32) { CP_WAIT1(); } else { CP_WAIT0(); }
        __syncthreads();   // stage kt&1 data visible to all warps

        int buf = kt & 1;
        uint32_t kBase = KV_u + (uint32_t)(buf * KVSTG) * 2 + kOff;
        uint32_t vBase = KV_u + (uint32_t)(buf * KVSTG) * 2 + vOff;

        // ---- S = Q @ K^T : this warp's 16 rows x 64 cols ----
        float s[8][4];
        #pragma unroll
        for (int nt = 0; nt < 8; nt++)
            #pragma unroll
            for (int k = 0; k < 4; k++) s[nt][k] = 0.f;

        #pragma unroll
        for (int ks = 0; ks < 4; ks++) {
            uint32_t a[4];
            LDSM_X4(a[0], a[1], a[2], a[3], qBase + (uint32_t)(ks * 16) * 2);
            uint32_t b[8][2];
            #pragma unroll
            for (int ntp = 0; ntp < 4; ntp++)
                LDSM_X4(b[2 * ntp][0], b[2 * ntp][1], b[2 * ntp + 1][0], b[2 * ntp + 1][1],
                        kBase + (uint32_t)(ntp * 16 * QLDH + ks * 16) * 2);
            #pragma unroll
            for (int nt = 0; nt < 8; nt++)
                mma_fp16(s[nt], a, b[nt]);
        }

        // ---- register online softmax ----
        float mx0 = -INFINITY, mx1 = -INFINITY;
        #pragma unroll
        for (int nt = 0; nt < 8; nt++) {
            mx0 = fmaxf(mx0, fmaxf(s[nt][0], s[nt][1]));
            mx1 = fmaxf(mx1, fmaxf(s[nt][2], s[nt][3]));
        }
        mx0 = fmaxf(mx0, __shfl_xor_sync(0xffffffffu, mx0, 1));
        mx0 = fmaxf(mx0, __shfl_xor_sync(0xffffffffu, mx0, 2));
        mx1 = fmaxf(mx1, __shfl_xor_sync(0xffffffffu, mx1, 1));
        mx1 = fmaxf(mx1, __shfl_xor_sync(0xffffffffu, mx1, 2));

        float mn0 = fmaxf(m0, mx0), mn1 = fmaxf(m1, mx1);
        float f0 = exp2f((m0 - mn0) * CEXP);
        float f1 = exp2f((m1 - mn1) * CEXP);

        float sum0 = 0.f, sum1 = 0.f;
        uint32_t p0[8], p1[8];
        #pragma unroll
        for (int nt = 0; nt < 8; nt++) {
            float e0 = exp2f((s[nt][0] - mn0) * CEXP);
            float e1 = exp2f((s[nt][1] - mn0) * CEXP);
            float e2 = exp2f((s[nt][2] - mn1) * CEXP);
            float e3 = exp2f((s[nt][3] - mn1) * CEXP);
            sum0 += e0 + e1;
            sum1 += e2 + e3;
            __half2 h0 = __floats2half2_rn(e0, e1);
            __half2 h1 = __floats2half2_rn(e2, e3);
            p0[nt] = *reinterpret_cast<uint32_t*>(&h0);
            p1[nt] = *reinterpret_cast<uint32_t*>(&h1);
        }
        sum0 += __shfl_xor_sync(0xffffffffu, sum0, 1);
        sum0 += __shfl_xor_sync(0xffffffffu, sum0, 2);
        sum1 += __shfl_xor_sync(0xffffffffu, sum1, 1);
        sum1 += __shfl_xor_sync(0xffffffffu, sum1, 2);

        l0 = l0 * f0 + sum0;  m0 = mn0;
        l1 = l1 * f1 + sum1;  m1 = mn1;

        #pragma unroll
        for (int nt = 0; nt < 8; nt++) {
            o[nt][0] *= f0; o[nt][1] *= f0;
            o[nt][2] *= f1; o[nt][3] *= f1;
        }

        // ---- O += P @ V : V via ldmatrix.trans ----
        #pragma unroll
        for (int kt2 = 0; kt2 < 4; kt2++) {
            uint32_t a[4] = { p0[2 * kt2], p1[2 * kt2], p0[2 * kt2 + 1], p1[2 * kt2 + 1] };
            uint32_t b[8][2];
            #pragma unroll
            for (int ntp = 0; ntp < 4; ntp++)
                LDSM_X4_T(b[2 * ntp][0], b[2 * ntp][1], b[2 * ntp + 1][0], b[2 * ntp + 1][1],
                          vBase + (uint32_t)(kt2 * 16 * QLDH + ntp * 16) * 2);
            #pragma unroll
            for (int nt = 0; nt < 8; nt++)
                mma_fp16(o[nt], a, b[nt]);
        }

        // all warps done reading stage kt&1 -> safe to overwrite with kt+2
        __syncthreads();
        if (kt + 2 < 32) { issue_kv(kt + 2, buf); CP_COMMIT(); }
    }

    // ---- finalize ----
    float i0 = 1.f / l0, i1 = 1.f / l1;
    size_t r0g = (size_t)bb * Lz + q0 + wid * 16 + qr;
    #pragma unroll
    for (int nt = 0; nt < 8; nt++) {
        int col = hh * Dz + nt * 8 + 2 * qc;
        *reinterpret_cast<__half2*>(&att[r0g * Ez + col]) =
            __floats2half2_rn(o[nt][0] * i0, o[nt][1] * i0);
        *reinterpret_cast<__half2*>(&att[(r0g + 8) * Ez + col]) =
            __floats2half2_rn(o[nt][2] * i1, o[nt][3] * i1);
    }
}

// ---------------- fused prep: LN1 + all 4 weight transposes in ONE launch ----------------
static __device__ __forceinline__ void dev_transpose(
    const float* __restrict__ src, __half* __restrict__ dst,
    int lds, int ldd, int bx, int by, float (*t)[33])
{
    int r0 = by * 32, c0 = bx * 32;
    int x = threadIdx.x & 31, y4 = (threadIdx.x >> 5) * 4;
    #pragma unroll
    for (int i = 0; i < 4; i++)
        t[y4 + i][x] = src[(long long)(r0 + y4 + i) * lds + c0 + x];
    __syncthreads();
    #pragma unroll
    for (int i = 0; i < 4; i++)
        dst[(long long)(c0 + y4 + i) * ldd + r0 + x] = __float2half_rn(t[x][y4 + i]);
}

static __device__ __forceinline__ void dev_ln(
    const float* __restrict__ x, const float* __restrict__ g,
    const float* __restrict__ b, __half* __restrict__ y, long long row,
    float* sh_s, float* sh_q)
{
    const float* xr = x + row * Ez;
    int t = threadIdx.x;

    float4 v = reinterpret_cast<const float4*>(xr)[t];
    float s  = v.x + v.y + v.z + v.w;
    float sq = v.x * v.x + v.y * v.y + v.z * v.z + v.w * v.w;
    #pragma unroll
    for (int o = 16; o > 0; o >>= 1) {
        s  += __shfl_down_sync(0xffffffffu, s,  o);
        sq += __shfl_down_sync(0xffffffffu, sq, o);
    }
    int warp = t >> 5, lane = t & 31;
    if (lane == 0) { sh_s[warp] = s; sh_q[warp] = sq; }
    __syncthreads();
    if (warp == 0) {
        s  = (lane < 8) ? sh_s[lane] : 0.f;
        sq = (lane < 8) ? sh_q[lane] : 0.f;
        #pragma unroll
        for (int o = 4; o > 0; o >>= 1) {
            s  += __shfl_down_sync(0xffffffffu, s,  o);
            sq += __shfl_down_sync(0xffffffffu, sq, o);
        }
        if (lane == 0) { sh_s[0] = s; sh_q[0] = sq; }
    }
    __syncthreads();
    float mu  = sh_s[0] * (1.f / Ez);
    float var = sh_q[0] * (1.f / Ez) - mu * mu;
    float inv = rsqrtf(var + 1e-5f);

    float4 gg = reinterpret_cast<const float4*>(g)[t];
    float4 bb = reinterpret_cast<const float4*>(b)[t];
    __half2 o0 = __floats2half2_rn((v.x - mu) * inv * gg.x + bb.x,
                                   (v.y - mu) * inv * gg.y + bb.y);
    __half2 o1 = __floats2half2_rn((v.z - mu) * inv * gg.z + bb.z,
                                   (v.w - mu) * inv * gg.w + bb.w);
    uint2 pk = make_uint2(*reinterpret_cast<uint32_t*>(&o0),
                          *reinterpret_cast<uint32_t*>(&o1));
    reinterpret_cast<uint2*>(y + row * Ez)[t] = pk;
}

__global__ void __launch_bounds__(256) prep_k(
    const float* __restrict__ x, const float* __restrict__ ln1_g, const float* __restrict__ ln1_b,
    __half* __restrict__ h,
    const float* __restrict__ Wqkv, __half* __restrict__ wqkvT,
    const float* __restrict__ Wproj, __half* __restrict__ wprojT,
    const float* __restrict__ W1, __half* __restrict__ w1T,
    const float* __restrict__ W2, __half* __restrict__ w2T)
{
    __shared__ float tbuf[32][33];
    __shared__ float sh_s[8];
    __shared__ float sh_q[8];

    int bid = blockIdx.x;
    if (bid < BLz) {
        dev_ln(x, ln1_g, ln1_b, h, bid, sh_s, sh_q);
        return;
    }
    bid -= BLz;
    if (bid < (E3z / 32) * (Ez / 32)) {
        dev_transpose(Wqkv, wqkvT, E3z, Ez, bid % (E3z / 32), bid / (E3z / 32), tbuf);
        return;
    }
    bid -= (E3z / 32) * (Ez / 32);
    if (bid < (Ez / 32) * (Ez / 32)) {
        dev_transpose(Wproj, wprojT, Ez, Ez, bid % (Ez / 32), bid / (Ez / 32), tbuf);
        return;
    }
    bid -= (Ez / 32) * (Ez / 32);
    if (bid < (FFz / 32) * (Ez / 32)) {
        dev_transpose(W1, w1T, FFz, Ez, bid % (FFz / 32), bid / (FFz / 32), tbuf);
        return;
    }
    bid -= (FFz / 32) * (Ez / 32);
    {
        dev_transpose(W2, w2T, Ez, FFz, bid % (Ez / 32), bid / (Ez / 32), tbuf);
    }
}

// ---------------- LayerNorm (standalone, for LN2) ----------------
__global__ __launch_bounds__(256) void ln_k(
    const float* __restrict__ x, const float* __restrict__ g,
    const float* __restrict__ b, __half* __restrict__ y)
{
    __shared__ float sh_s[8];
    __shared__ float sh_q[8];
    dev_ln(x, g, b, y, blockIdx.x, sh_s, sh_q);
}

// ---------------- driver ----------------
extern "C" void kernel_launch(void* const* d_in, const int* in_sizes, int n_in,
                              void* d_out, int out_size)
{
    (void)in_sizes; (void)n_in; (void)out_size;
    const float* x      = (const float*)d_in[0];
    const float* ln1_g  = (const float*)d_in[1];
    const float* ln1_b  = (const float*)d_in[2];
    const float* W_qkv  = (const float*)d_in[3];
    const float* W_proj = (const float*)d_in[4];
    const float* b_proj = (const float*)d_in[5];
    const float* ln2_g  = (const float*)d_in[6];
    const float* ln2_b  = (const float*)d_in[7];
    const float* W1     = (const float*)d_in[8];
    const float* b1     = (const float*)d_in[9];
    const float* W2     = (const float*)d_in[10];
    const float* b2     = (const float*)d_in[11];
    float* out = (float*)d_out;

    __half *h, *qkv, *att, *ffn, *wqkvT, *wprojT, *w1T, *w2T;
    float *x1;
    cudaGetSymbolAddress((void**)&h,      g_h);
    cudaGetSymbolAddress((void**)&qkv,    g_qkv);
    cudaGetSymbolAddress((void**)&att,    g_att);
    cudaGetSymbolAddress((void**)&x1,     g_x1);
    cudaGetSymbolAddress((void**)&ffn,    g_ffn);
    cudaGetSymbolAddress((void**)&wqkvT,  g_wqkvT);
    cudaGetSymbolAddress((void**)&wprojT, g_wprojT);
    cudaGetSymbolAddress((void**)&w1T,    g_w1T);
    cudaGetSymbolAddress((void**)&w2T,    g_w2T);

    const int SMG = 3 * 2 * 128 * SLDH * 2;              // 110592 bytes (3-stage, 128x128)
    const int FLASH_SMEM = (128 * QLDH + 2 * KVSTG) * 2; // 55296 bytes
    cudaFuncSetAttribute(mma_gemm<EPI_NONE,      true >, cudaFuncAttributeMaxDynamicSharedMemorySize, SMG);
    cudaFuncSetAttribute(mma_gemm<EPI_BIAS_RES,  false>, cudaFuncAttributeMaxDynamicSharedMemorySize, SMG);
    cudaFuncSetAttribute(mma_gemm<EPI_BIAS_GELU, true >, cudaFuncAttributeMaxDynamicSharedMemorySize, SMG);
    cudaFuncSetAttribute(flash_k, cudaFuncAttributeMaxDynamicSharedMemorySize, FLASH_SMEM);

    // 1. prep: LN1 + all weight transposes, one launch
    const int PREP_BLOCKS = BLz + (E3z / 32) * (Ez / 32) + (Ez / 32) * (Ez / 32)
                          + (FFz / 32) * (Ez / 32) + (Ez / 32) * (FFz / 32);
    prep_k<<<PREP_BLOCKS, 256>>>(x, ln1_g, ln1_b, h,
                                 W_qkv, wqkvT, W_proj, wprojT, W1, w1T, W2, w2T);

    // 2. qkv = fp16(h @ W_qkv)
    mma_gemm<EPI_NONE, true><<<dim3(E3z / 128, BLz / 128, 1), 256, SMG>>>(
        h, wqkvT, qkv, nullptr, nullptr, Ez, Ez, Ez, E3z);

    // 3. att = flash(Q, K, V)  — cp.async-pipelined K/V
    flash_k<<<dim3(Lz / 128, Bz * Hz), 256, FLASH_SMEM>>>(qkv, att);

    // 4. x1 = x + att @ W_proj + b_proj   (fp32)
    mma_gemm<EPI_BIAS_RES, false><<<dim3(Ez / 128, BLz / 128, 1), 256, SMG>>>(
        att, wprojT, x1, b_proj, x, Ez, Ez, Ez, Ez);

    // 5. h = fp16(LN2(x1))
    ln_k<<<BLz, 256>>>(x1, ln2_g, ln2_b, h);

    // 6. ffn = fp16(gelu(h @ W1 + b1))
    mma_gemm<EPI_BIAS_GELU, true><<<dim3(FFz / 128, BLz / 128, 1), 256, SMG>>>(
        h, w1T, ffn, b1, nullptr, Ez, Ez, Ez, FFz);

    // 7. out = x1 + ffn @ W2 + b2   (fp32 final output)
    mma_gemm<EPI_BIAS_RES, false><<<dim3(Ez / 128, BLz / 128, 1), 256, SMG>>>(
        ffn, w2T, out, b2, x1, FFz, FFz, FFz, Ez);
}